// round 1
// baseline (speedup 1.0000x reference)
#include <cuda_runtime.h>

#define SQ 256      // sequence length
#define DH 32       // head dim
#define KPAD 36     // padded K row stride (floats) for conflict-free LDS.128

// smem layout (floats):
//   Ks: 256*36  = 9216
//   Vs: 256*32  = 8192
//   Ms: 256
//   Ps: 8*256   = 2048
// total 19712 floats = 78848 bytes
#define SMEM_FLOATS (SQ*KPAD + SQ*DH + SQ + 8*SQ)

__global__ __launch_bounds__(256, 2)
void TFA_88089779241014_kernel(const float* __restrict__ q,
                               const float* __restrict__ k,
                               const float* __restrict__ v,
                               const float* __restrict__ mask,
                               const float* __restrict__ tri,
                               float* __restrict__ out) {
    extern __shared__ float sm[];
    float* Ks = sm;                  // [256][36]
    float* Vs = Ks + SQ * KPAD;      // [256][32]
    float* Ms = Vs + SQ * DH;        // [256]
    float* Ps = Ms + SQ;             // [8][256] (one row per warp)

    const int bx   = blockIdx.x;     // n*4 + h
    const int n    = bx >> 2;
    const int h    = bx & 3;
    const int tid  = threadIdx.x;
    const int lane = tid & 31;
    const int wid  = tid >> 5;

    const float* qb = q   + (size_t)bx * SQ * DH;
    const float* kb = k   + (size_t)bx * SQ * DH;
    const float* vb = v   + (size_t)bx * SQ * DH;
    float*       ob = out + (size_t)bx * SQ * DH;
    const float* mb = mask + (size_t)n * SQ;
    const float* tb = tri  + (size_t)h * SQ * SQ;

    // ---- stage K (padded) and V (linear) into smem, coalesced float4 ----
    for (int i = tid; i < SQ * DH / 4; i += 256) {
        float4 kk = ((const float4*)kb)[i];
        int row = i >> 3;            // 8 float4 per row
        int col = (i & 7) << 2;
        *(float4*)&Ks[row * KPAD + col] = kk;
        ((float4*)Vs)[i] = ((const float4*)vb)[i];
    }
    Ms[tid] = mb[tid];
    __syncthreads();

    const float scale = 0.17677669529663687f;   // 1/sqrt(32)
    float* Pw = Ps + wid * SQ;                  // warp-private P row

    for (int qt = 0; qt < SQ / 8; qt++) {
        const int s = qt * 8 + wid;             // this warp's query row

        // q row into registers (uniform-address LDG, broadcast)
        float4 qv[8];
        const float4* qr = (const float4*)(qb + s * DH);
        #pragma unroll
        for (int i = 0; i < 8; i++) qv[i] = qr[i];

        // prefetch triangle bias for this lane's 8 keys (coalesced, L2-resident)
        float trir[8];
        const float* tr = tb + (size_t)s * SQ;
        #pragma unroll
        for (int j = 0; j < 8; j++) trir[j] = tr[j * 32 + lane];

        // ---- QK^T: lane handles keys t = 32j + lane ----
        float sc[8];
        #pragma unroll
        for (int j = 0; j < 8; j++) {
            const int t = j * 32 + lane;
            const float* kr = &Ks[t * KPAD];
            float acc = 0.f;
            #pragma unroll
            for (int d4 = 0; d4 < 8; d4++) {
                float4 kk = *(const float4*)&kr[d4 * 4];
                acc += qv[d4].x * kk.x;
                acc += qv[d4].y * kk.y;
                acc += qv[d4].z * kk.z;
                acc += qv[d4].w * kk.w;
            }
            sc[j] = acc * scale + Ms[t] + trir[j];
        }

        // ---- softmax (warp reduction) ----
        float m = sc[0];
        #pragma unroll
        for (int j = 1; j < 8; j++) m = fmaxf(m, sc[j]);
        #pragma unroll
        for (int o = 16; o > 0; o >>= 1)
            m = fmaxf(m, __shfl_xor_sync(0xffffffffu, m, o));

        float sum = 0.f;
        #pragma unroll
        for (int j = 0; j < 8; j++) { sc[j] = __expf(sc[j] - m); sum += sc[j]; }
        #pragma unroll
        for (int o = 16; o > 0; o >>= 1)
            sum += __shfl_xor_sync(0xffffffffu, sum, o);
        const float rinv = 1.f / sum;

        #pragma unroll
        for (int j = 0; j < 8; j++) Pw[j * 32 + lane] = sc[j] * rinv;
        __syncwarp();

        // ---- PV: lane = output dim d; P broadcast LDS.128, V conflict-free ----
        float acc = 0.f;
        #pragma unroll 8
        for (int t4 = 0; t4 < SQ / 4; t4++) {
            float4 pp = *(const float4*)&Pw[t4 * 4];
            acc += pp.x * Vs[(t4 * 4 + 0) * DH + lane];
            acc += pp.y * Vs[(t4 * 4 + 1) * DH + lane];
            acc += pp.z * Vs[(t4 * 4 + 2) * DH + lane];
            acc += pp.w * Vs[(t4 * 4 + 3) * DH + lane];
        }
        ob[s * DH + lane] = acc;
        __syncwarp();   // protect Pw before next tile overwrites it
    }
}

extern "C" void kernel_launch(void* const* d_in, const int* in_sizes, int n_in,
                              void* d_out, int out_size) {
    const float* q    = (const float*)d_in[0];
    const float* k    = (const float*)d_in[1];
    const float* v    = (const float*)d_in[2];
    const float* mask = (const float*)d_in[3];
    const float* tri  = (const float*)d_in[4];
    float* out = (float*)d_out;

    const int smem_bytes = SMEM_FLOATS * sizeof(float);   // 78848
    cudaFuncSetAttribute(TFA_88089779241014_kernel,
                         cudaFuncAttributeMaxDynamicSharedMemorySize, smem_bytes);

    // one CTA per (n, h) head: 256*4 = 1024 CTAs
    TFA_88089779241014_kernel<<<1024, 256, smem_bytes>>>(q, k, v, mask, tri, out);
}

// round 2
// speedup vs baseline: 1.0009x; 1.0009x over previous
#include <cuda_runtime.h>

#define SQ 256      // sequence length
#define DH 32       // head dim
#define KPAD 36     // padded K row stride (floats) for conflict-free LDS.128

// smem layout (floats):
//   Ks: 256*36  = 9216
//   Vs: 256*32  = 8192
//   Ms: 256
//   Ps: 8*256   = 2048
// total 19712 floats = 78848 bytes
#define SMEM_FLOATS (SQ*KPAD + SQ*DH + SQ + 8*SQ)

__global__ __launch_bounds__(256, 2)
void TFA_88089779241014_kernel(const float* __restrict__ q,
                               const float* __restrict__ k,
                               const float* __restrict__ v,
                               const float* __restrict__ mask,
                               const float* __restrict__ tri,
                               float* __restrict__ out) {
    extern __shared__ float sm[];
    float* Ks = sm;                  // [256][36]
    float* Vs = Ks + SQ * KPAD;      // [256][32]
    float* Ms = Vs + SQ * DH;        // [256]
    float* Ps = Ms + SQ;             // [8][256] (one row per warp)

    const int bx   = blockIdx.x;     // n*4 + h
    const int n    = bx >> 2;
    const int h    = bx & 3;
    const int tid  = threadIdx.x;
    const int lane = tid & 31;
    const int wid  = tid >> 5;

    const float* qb = q   + (size_t)bx * SQ * DH;
    const float* kb = k   + (size_t)bx * SQ * DH;
    const float* vb = v   + (size_t)bx * SQ * DH;
    float*       ob = out + (size_t)bx * SQ * DH;
    const float* mb = mask + (size_t)n * SQ;
    const float* tb = tri  + (size_t)h * SQ * SQ;

    // ---- stage K (padded) and V (linear) into smem, coalesced float4 ----
    for (int i = tid; i < SQ * DH / 4; i += 256) {
        float4 kk = ((const float4*)kb)[i];
        int row = i >> 3;            // 8 float4 per row
        int col = (i & 7) << 2;
        *(float4*)&Ks[row * KPAD + col] = kk;
        ((float4*)Vs)[i] = ((const float4*)vb)[i];
    }
    Ms[tid] = mb[tid];
    __syncthreads();

    const float scale = 0.17677669529663687f;   // 1/sqrt(32)
    float* Pw = Ps + wid * SQ;                  // warp-private P row

    for (int qt = 0; qt < SQ / 8; qt++) {
        const int s = qt * 8 + wid;             // this warp's query row

        // q row into registers (uniform-address LDG, broadcast)
        float4 qv[8];
        const float4* qr = (const float4*)(qb + s * DH);
        #pragma unroll
        for (int i = 0; i < 8; i++) qv[i] = qr[i];

        // prefetch triangle bias for this lane's 8 keys (coalesced, L2-resident)
        float trir[8];
        const float* tr = tb + (size_t)s * SQ;
        #pragma unroll
        for (int j = 0; j < 8; j++) trir[j] = tr[j * 32 + lane];

        // ---- QK^T: lane handles keys t = 32j + lane ----
        float sc[8];
        #pragma unroll
        for (int j = 0; j < 8; j++) {
            const int t = j * 32 + lane;
            const float* kr = &Ks[t * KPAD];
            float acc = 0.f;
            #pragma unroll
            for (int d4 = 0; d4 < 8; d4++) {
                float4 kk = *(const float4*)&kr[d4 * 4];
                acc += qv[d4].x * kk.x;
                acc += qv[d4].y * kk.y;
                acc += qv[d4].z * kk.z;
                acc += qv[d4].w * kk.w;
            }
            sc[j] = acc * scale + Ms[t] + trir[j];
        }

        // ---- softmax (warp reduction) ----
        float m = sc[0];
        #pragma unroll
        for (int j = 1; j < 8; j++) m = fmaxf(m, sc[j]);
        #pragma unroll
        for (int o = 16; o > 0; o >>= 1)
            m = fmaxf(m, __shfl_xor_sync(0xffffffffu, m, o));

        float sum = 0.f;
        #pragma unroll
        for (int j = 0; j < 8; j++) { sc[j] = __expf(sc[j] - m); sum += sc[j]; }
        #pragma unroll
        for (int o = 16; o > 0; o >>= 1)
            sum += __shfl_xor_sync(0xffffffffu, sum, o);
        const float rinv = 1.f / sum;

        #pragma unroll
        for (int j = 0; j < 8; j++) Pw[j * 32 + lane] = sc[j] * rinv;
        __syncwarp();

        // ---- PV: lane = output dim d; P broadcast LDS.128, V conflict-free ----
        float acc = 0.f;
        #pragma unroll 8
        for (int t4 = 0; t4 < SQ / 4; t4++) {
            float4 pp = *(const float4*)&Pw[t4 * 4];
            acc += pp.x * Vs[(t4 * 4 + 0) * DH + lane];
            acc += pp.y * Vs[(t4 * 4 + 1) * DH + lane];
            acc += pp.z * Vs[(t4 * 4 + 2) * DH + lane];
            acc += pp.w * Vs[(t4 * 4 + 3) * DH + lane];
        }
        ob[s * DH + lane] = acc;
        __syncwarp();   // protect Pw before next tile overwrites it
    }
}

extern "C" void kernel_launch(void* const* d_in, const int* in_sizes, int n_in,
                              void* d_out, int out_size) {
    const float* q    = (const float*)d_in[0];
    const float* k    = (const float*)d_in[1];
    const float* v    = (const float*)d_in[2];
    const float* mask = (const float*)d_in[3];
    const float* tri  = (const float*)d_in[4];
    float* out = (float*)d_out;

    const int smem_bytes = SMEM_FLOATS * sizeof(float);   // 78848
    cudaFuncSetAttribute(TFA_88089779241014_kernel,
                         cudaFuncAttributeMaxDynamicSharedMemorySize, smem_bytes);

    // one CTA per (n, h) head: 256*4 = 1024 CTAs
    TFA_88089779241014_kernel<<<1024, 256, smem_bytes>>>(q, k, v, mask, tri, out);
}